// round 2
// baseline (speedup 1.0000x reference)
#include <cuda_runtime.h>
#include <math.h>

#define NN 1024
#define BB 64
#define TT 12
#define HH 64
#define CC 2

// ---------------- static device scratch (no allocations allowed) ----------------
__device__ float g_xT[TT * NN * BB * CC];          // x transposed to [t][i][b][c]
__device__ float g_GT[4 * NN * NN];                // non-identity supports, transposed [kk][j][i]
__device__ float g_comb[NN * BB * 128];            // [i][b][p]
__device__ float g_S[NN * BB * 768];               // [i][b][k*P+p]
__device__ float g_z[NN * BB * HH];                // gate z, [m][h]
__device__ float g_h0[NN * BB * HH];
__device__ float g_h1[NN * BB * HH];
__device__ float g_y[NN * BB * CC];                // decoder feedback input

// ---------------- utility kernels ----------------
__global__ void k_zero(float* __restrict__ p, int n) {
    int e = blockIdx.x * blockDim.x + threadIdx.x;
    if (e < n) p[e] = 0.f;
}

__global__ void k_transpose_x(const float* __restrict__ x) {
    int e = blockIdx.x * blockDim.x + threadIdx.x;
    if (e >= TT * NN * BB * CC) return;
    int c = e % CC;
    int b = (e / CC) % BB;
    int i = (e / (CC * BB)) % NN;
    int t = e / (CC * BB * NN);
    g_xT[e] = x[(((size_t)b * TT + t) * NN + i) * CC + c];
}

// Transpose the 4 non-identity supports: GT[kk][j][i] = G[kmap[kk]][i][j]
__global__ void k_transpose_G(const float* __restrict__ G) {
    __shared__ float tile[32][33];
    const int kmap[4] = {1, 2, 4, 5};
    int kk = blockIdx.z;
    const float* A = G + (size_t)kmap[kk] * NN * NN;
    float* Bp = g_GT + (size_t)kk * NN * NN;
    int i0 = blockIdx.y * 32, j0 = blockIdx.x * 32;
#pragma unroll
    for (int s = 0; s < 32; s += 8)
        tile[threadIdx.y + s][threadIdx.x] =
            A[(size_t)(i0 + threadIdx.y + s) * NN + j0 + threadIdx.x];
    __syncthreads();
#pragma unroll
    for (int s = 0; s < 32; s += 8)
        Bp[(size_t)(j0 + threadIdx.y + s) * NN + i0 + threadIdx.x] =
            tile[threadIdx.x][threadIdx.y + s];
}

// comb[i][b][p] = concat(xin, h); also fill S slices k=0 and k=3 (identity supports)
__global__ void k_build_comb(const float* __restrict__ xin, const float* __restrict__ h,
                             int Pin, int P, int KP) {
    int e = blockIdx.x * blockDim.x + threadIdx.x;
    int total = NN * BB * P;
    if (e >= total) return;
    int p = e % P;
    int ib = e / P;
    float v = (p < Pin) ? xin[ib * Pin + p] : h[ib * HH + (p - Pin)];
    g_comb[e] = v;
    size_t base = (size_t)ib * KP;
    g_S[base + p] = v;            // k = 0 (identity)
    g_S[base + 3 * P + p] = v;    // k = 3 (identity)
}

#define MICRO_FMA(a, b)                                                        \
    acc[0][0] += a.x * b.x; acc[0][1] += a.x * b.y;                            \
    acc[0][2] += a.x * b.z; acc[0][3] += a.x * b.w;                            \
    acc[1][0] += a.y * b.x; acc[1][1] += a.y * b.y;                            \
    acc[1][2] += a.y * b.z; acc[1][3] += a.y * b.w;                            \
    acc[2][0] += a.z * b.x; acc[2][1] += a.z * b.y;                            \
    acc[2][2] += a.z * b.z; acc[2][3] += a.z * b.w;                            \
    acc[3][0] += a.w * b.x; acc[3][1] += a.w * b.y;                            \
    acc[3][2] += a.w * b.z; acc[3][3] += a.w * b.w;

// C[i, c] = sum_j GT[kk][j][i] * comb[j][c], c = b*P+p;  store into S[i][b][k*P+p]
// grid (P, 16, 4), block 256
__global__ void __launch_bounds__(256) k_gcn_gemm(int P) {
    const int kmap[4] = {1, 2, 4, 5};
    int kk = blockIdx.z;
    int BP = BB * P, KP = 6 * P;
    const float* A = g_GT + (size_t)kk * NN * NN;
    int i0 = blockIdx.y * 64, c0 = blockIdx.x * 64;
    __shared__ __align__(16) float As[16][64];   // As[j_local][i_local]
    __shared__ __align__(16) float Bs[16][64];   // Bs[j_local][c_local]
    int tid = threadIdx.x, tx = tid & 15, ty = tid >> 4;
    float acc[4][4] = {};
    for (int j0 = 0; j0 < NN; j0 += 16) {
#pragma unroll
        for (int l = 0; l < 4; l++) {
            int idx = tid + l * 256;
            int r = idx >> 6, cc = idx & 63;
            As[r][cc] = A[(size_t)(j0 + r) * NN + i0 + cc];
            Bs[r][cc] = g_comb[(size_t)(j0 + r) * BP + c0 + cc];
        }
        __syncthreads();
#pragma unroll
        for (int q = 0; q < 16; q++) {
            float4 a = *(const float4*)&As[q][ty * 4];
            float4 b = *(const float4*)&Bs[q][tx * 4];
            MICRO_FMA(a, b)
        }
        __syncthreads();
    }
    int k = kmap[kk];
#pragma unroll
    for (int r = 0; r < 4; r++) {
        int i = i0 + ty * 4 + r;
#pragma unroll
        for (int cc = 0; cc < 4; cc++) {
            int c = c0 + tx * 4 + cc;
            int b = c / P;
            int p = c - b * P;
            g_S[(size_t)i * BB * KP + (size_t)b * KP + k * P + p] = acc[r][cc];
        }
    }
}

// zr = sigmoid(S @ gW + gb); z -> g_z, r*h -> comb[:, Pin:] AND into the
// identity S slices (k=0 and k=3), so S stays consistent with comb2 = [x, r*h].
// grid (2, 1024), block 256
__global__ void __launch_bounds__(256) k_gate_gemm(const float* __restrict__ W,
                                                   const float* __restrict__ bias,
                                                   const float* __restrict__ h, int P) {
    int KP = 6 * P;
    int m0 = blockIdx.y * 64, n0 = blockIdx.x * 64;
    __shared__ __align__(16) float As[12][68];   // As[k_local][m_local] (transposed)
    __shared__ __align__(16) float Bs[12][64];
    int tid = threadIdx.x, tx = tid & 15, ty = tid >> 4;
    float acc[4][4] = {};
    for (int k0 = 0; k0 < KP; k0 += 12) {
#pragma unroll
        for (int l = 0; l < 3; l++) {
            int idx = tid + l * 256;
            int r = idx / 12, cc = idx - r * 12;
            As[cc][r] = g_S[(size_t)(m0 + r) * KP + k0 + cc];
            int r2 = idx >> 6, c2 = idx & 63;
            Bs[r2][c2] = W[(k0 + r2) * 128 + n0 + c2];
        }
        __syncthreads();
#pragma unroll
        for (int q = 0; q < 12; q++) {
            float4 a = *(const float4*)&As[q][ty * 4];
            float4 b = *(const float4*)&Bs[q][tx * 4];
            MICRO_FMA(a, b)
        }
        __syncthreads();
    }
    int Pin = P - HH;
#pragma unroll
    for (int r = 0; r < 4; r++) {
        int m = m0 + ty * 4 + r;
#pragma unroll
        for (int cc = 0; cc < 4; cc++) {
            int n = n0 + tx * 4 + cc;
            float v = acc[r][cc] + bias[n];
            v = 1.f / (1.f + expf(-v));
            if (n < HH) {
                g_z[m * HH + n] = v;
            } else {
                int hc = n - HH;
                float rh = v * h[m * HH + hc];
                g_comb[(size_t)m * P + Pin + hc] = rh;
                // keep identity S slices in sync with comb2 = [x, r*h]
                size_t sbase = (size_t)m * KP;
                g_S[sbase + Pin + hc] = rh;           // k = 0 (identity)
                g_S[sbase + 3 * P + Pin + hc] = rh;   // k = 3 (identity)
            }
        }
    }
}

// n = tanh(S2 @ uW + ub); h = z*n + (1-z)*h   (in place)
// grid (1, 1024), block 256
__global__ void __launch_bounds__(256) k_update_gemm(const float* __restrict__ W,
                                                     const float* __restrict__ bias,
                                                     float* __restrict__ h, int P) {
    int KP = 6 * P;
    int m0 = blockIdx.y * 64;
    __shared__ __align__(16) float As[12][68];
    __shared__ __align__(16) float Bs[12][64];
    int tid = threadIdx.x, tx = tid & 15, ty = tid >> 4;
    float acc[4][4] = {};
    for (int k0 = 0; k0 < KP; k0 += 12) {
#pragma unroll
        for (int l = 0; l < 3; l++) {
            int idx = tid + l * 256;
            int r = idx / 12, cc = idx - r * 12;
            As[cc][r] = g_S[(size_t)(m0 + r) * KP + k0 + cc];
            int r2 = idx >> 6, c2 = idx & 63;
            Bs[r2][c2] = W[(k0 + r2) * HH + c2];
        }
        __syncthreads();
#pragma unroll
        for (int q = 0; q < 12; q++) {
            float4 a = *(const float4*)&As[q][ty * 4];
            float4 b = *(const float4*)&Bs[q][tx * 4];
            MICRO_FMA(a, b)
        }
        __syncthreads();
    }
#pragma unroll
    for (int r = 0; r < 4; r++) {
        int m = m0 + ty * 4 + r;
#pragma unroll
        for (int cc = 0; cc < 4; cc++) {
            int n = tx * 4 + cc;
            float nv = tanhf(acc[r][cc] + bias[n]);
            float zv = g_z[m * HH + n];
            float hv = h[m * HH + n];
            h[m * HH + n] = zv * nv + (1.f - zv) * hv;
        }
    }
}

// y = h1 @ projW + projb; also write output slice t.  out layout [B, HOR, N, C]
__global__ void k_proj(const float* __restrict__ h1, const float* __restrict__ Wp,
                       const float* __restrict__ bp, float* __restrict__ out, int t) {
    int e = blockIdx.x * blockDim.x + threadIdx.x;
    if (e >= NN * BB * CC) return;
    int c = e & 1;
    int m = e >> 1;
    float s = bp[c];
#pragma unroll
    for (int hh = 0; hh < HH; hh++) s += h1[m * HH + hh] * Wp[hh * CC + c];
    g_y[e] = s;
    int i = m >> 6, b = m & 63;
    out[(((size_t)b * TT + t) * NN + i) * CC + c] = s;
}

// ---------------- host orchestration ----------------
static void run_cell(const float* xin, int Pin, float* h,
                     const float* gW, const float* gb,
                     const float* uW, const float* ub) {
    int P = Pin + HH;
    int total = NN * BB * P;
    k_build_comb<<<(total + 255) / 256, 256>>>(xin, h, Pin, P, 6 * P);
    dim3 gg(P, 16, 4);
    k_gcn_gemm<<<gg, 256>>>(P);
    k_gate_gemm<<<dim3(2, 1024), 256>>>(gW, gb, h, P);
    k_gcn_gemm<<<gg, 256>>>(P);
    k_update_gemm<<<dim3(1, 1024), 256>>>(uW, ub, h, P);
}

extern "C" void kernel_launch(void* const* d_in, const int* in_sizes, int n_in,
                              void* d_out, int out_size) {
    const float* x = (const float*)d_in[0];
    const float* G = (const float*)d_in[1];
    const float* gW[4] = {(const float*)d_in[2], (const float*)d_in[6],
                          (const float*)d_in[10], (const float*)d_in[14]};
    const float* gb[4] = {(const float*)d_in[3], (const float*)d_in[7],
                          (const float*)d_in[11], (const float*)d_in[15]};
    const float* uW[4] = {(const float*)d_in[4], (const float*)d_in[8],
                          (const float*)d_in[12], (const float*)d_in[16]};
    const float* ub[4] = {(const float*)d_in[5], (const float*)d_in[9],
                          (const float*)d_in[13], (const float*)d_in[17]};
    const float* projW = (const float*)d_in[18];
    const float* projb = (const float*)d_in[19];
    float* out = (float*)d_out;

    float *h0, *h1, *y, *xT;
    cudaGetSymbolAddress((void**)&h0, g_h0);
    cudaGetSymbolAddress((void**)&h1, g_h1);
    cudaGetSymbolAddress((void**)&y, g_y);
    cudaGetSymbolAddress((void**)&xT, g_xT);

    k_transpose_x<<<(TT * NN * BB * CC + 255) / 256, 256>>>(x);
    k_transpose_G<<<dim3(32, 32, 4), dim3(32, 8)>>>(G);
    k_zero<<<(NN * BB * HH + 255) / 256, 256>>>(h0, NN * BB * HH);
    k_zero<<<(NN * BB * HH + 255) / 256, 256>>>(h1, NN * BB * HH);
    k_zero<<<(NN * BB * CC + 255) / 256, 256>>>(y, NN * BB * CC);

    // encoder: 2 layers, 12 steps (interleaved so only current h0 is needed)
    for (int t = 0; t < TT; t++) {
        run_cell(xT + (size_t)t * NN * BB * CC, CC, h0, gW[0], gb[0], uW[0], ub[0]);
        run_cell(h0, HH, h1, gW[1], gb[1], uW[1], ub[1]);
    }
    // decoder: states continue from encoder finals (h0, h1 reused in place)
    for (int t = 0; t < TT; t++) {
        run_cell(y, CC, h0, gW[2], gb[2], uW[2], ub[2]);
        run_cell(h0, HH, h1, gW[3], gb[3], uW[3], ub[3]);
        k_proj<<<(NN * BB * CC + 255) / 256, 256>>>(h1, projW, projb, out, t);
    }
}

// round 4
// speedup vs baseline: 1.5208x; 1.5208x over previous
#include <cuda_runtime.h>
#include <math.h>
#include <stdint.h>

#define NN 1024
#define BB 64
#define TT 12
#define HH 64
#define CC 2

// ---------------- static device scratch (no allocations allowed) ----------------
__device__ float g_xT[TT * NN * BB * CC];          // x transposed to [t][i][b][c]
__device__ float g_GThi[4 * NN * NN];              // non-identity supports, transposed, tf32-hi
__device__ float g_GTlo[4 * NN * NN];              // residual lo part (tf32)
__device__ float g_comb[NN * BB * 128];            // [i][b][p]
__device__ float g_S[NN * BB * 768];               // [i][b][k*P+p]
__device__ float g_z[NN * BB * HH];                // gate z, [m][h]
__device__ float g_h0[NN * BB * HH];
__device__ float g_h1[NN * BB * HH];
__device__ float g_y[NN * BB * CC];                // decoder feedback input

__device__ __forceinline__ float tf32_rna(float v) {
    uint32_t u;
    asm("cvt.rna.tf32.f32 %0, %1;" : "=r"(u) : "f"(v));
    return __uint_as_float(u);
}

// ---------------- utility kernels ----------------
__global__ void k_zero(float* __restrict__ p, int n) {
    int e = blockIdx.x * blockDim.x + threadIdx.x;
    if (e < n) p[e] = 0.f;
}

__global__ void k_transpose_x(const float* __restrict__ x) {
    int e = blockIdx.x * blockDim.x + threadIdx.x;
    if (e >= TT * NN * BB * CC) return;
    int c = e % CC;
    int b = (e / CC) % BB;
    int i = (e / (CC * BB)) % NN;
    int t = e / (CC * BB * NN);
    g_xT[e] = x[(((size_t)b * TT + t) * NN + i) * CC + c];
}

// Transpose the 4 non-identity supports and split into tf32 hi/lo:
// GThi/lo[kk][j][i] = split(G[kmap[kk]][i][j])
__global__ void k_transpose_G(const float* __restrict__ G) {
    __shared__ float tile[32][33];
    const int kmap[4] = {1, 2, 4, 5};
    int kk = blockIdx.z;
    const float* A = G + (size_t)kmap[kk] * NN * NN;
    float* Hi = g_GThi + (size_t)kk * NN * NN;
    float* Lo = g_GTlo + (size_t)kk * NN * NN;
    int i0 = blockIdx.y * 32, j0 = blockIdx.x * 32;
#pragma unroll
    for (int s = 0; s < 32; s += 8)
        tile[threadIdx.y + s][threadIdx.x] =
            A[(size_t)(i0 + threadIdx.y + s) * NN + j0 + threadIdx.x];
    __syncthreads();
#pragma unroll
    for (int s = 0; s < 32; s += 8) {
        float v = tile[threadIdx.x][threadIdx.y + s];
        float hi = tf32_rna(v);
        float lo = tf32_rna(v - hi);
        size_t o = (size_t)(j0 + threadIdx.y + s) * NN + i0 + threadIdx.x;
        Hi[o] = hi;
        Lo[o] = lo;
    }
}

// comb[i][b][p] = concat(xin, h); also fill S slices k=0 and k=3 (identity supports)
__global__ void k_build_comb(const float* __restrict__ xin, const float* __restrict__ h,
                             int Pin, int P, int KP) {
    int e = blockIdx.x * blockDim.x + threadIdx.x;
    int total = NN * BB * P;
    if (e >= total) return;
    int p = e % P;
    int ib = e / P;
    float v = (p < Pin) ? xin[ib * Pin + p] : h[ib * HH + (p - Pin)];
    g_comb[e] = v;
    size_t base = (size_t)ib * KP;
    g_S[base + p] = v;            // k = 0 (identity)
    g_S[base + 3 * P + p] = v;    // k = 3 (identity)
}

// ---------------- 3xTF32 tensor-core GCN GEMM ----------------
// S[i][b][k*P + col_off + p] = sum_j GT[kk][j][i] * comb[j][b*P + col_off + p]
// cols_per_b: P (full, GCN1) or 64 (h-columns only, GCN2); col_off: 0 or Pin.
// Block tile 128(i) x 64(c), BLK_K=16, 8 warps of 32x32.
#define MMA_TF32(d, a, b)                                                      \
    asm volatile(                                                              \
        "mma.sync.aligned.m16n8k8.row.col.f32.tf32.tf32.f32 "                  \
        "{%0,%1,%2,%3}, {%4,%5,%6,%7}, {%8,%9}, {%0,%1,%2,%3};"                \
        : "+f"(d[0]), "+f"(d[1]), "+f"(d[2]), "+f"(d[3])                       \
        : "r"(a[0]), "r"(a[1]), "r"(a[2]), "r"(a[3]), "r"(b[0]), "r"(b[1]));

__global__ void __launch_bounds__(256) k_gcn_mma(int P, int cols_per_b, int col_off) {
    const int kmap[4] = {1, 2, 4, 5};
    int kk = blockIdx.z;
    int KP = 6 * P, BP = BB * P;
    const float* Ahi_g = g_GThi + (size_t)kk * NN * NN;
    const float* Alo_g = g_GTlo + (size_t)kk * NN * NN;
    int i0 = blockIdx.y * 128, c0 = blockIdx.x * 64;

    __shared__ __align__(16) float sAhi[16][136];
    __shared__ __align__(16) float sAlo[16][136];
    __shared__ __align__(16) float sBhi[16][72];
    __shared__ __align__(16) float sBlo[16][72];

    int tid = threadIdx.x;
    int w = tid >> 5, lane = tid & 31, lr = lane >> 2, lc = lane & 3;
    int wm = w & 3, wn = w >> 2;           // warp tile: (wm*32, wn*32)

    // precompute B-tile column mapping (constant across k loop)
    int bcol[4], bsrc[4];
#pragma unroll
    for (int l = 0; l < 4; l++) {
        int lin = tid + l * 256;
        int ccol = lin & 63;
        int gc = c0 + ccol;
        int b = gc / cols_per_b;
        int p = gc - b * cols_per_b;
        bcol[l] = ccol;
        bsrc[l] = b * P + col_off + p;
    }

    float acc[2][4][4] = {};

    for (int j0 = 0; j0 < NN; j0 += 16) {
        // load A tile (16 x 128) hi+lo, float4
#pragma unroll
        for (int l = 0; l < 2; l++) {
            int lin = tid + l * 256;
            int r = lin >> 5, c4 = (lin & 31) * 4;
            size_t go = (size_t)(j0 + r) * NN + i0 + c4;
            *(float4*)&sAhi[r][c4] = *(const float4*)&Ahi_g[go];
            *(float4*)&sAlo[r][c4] = *(const float4*)&Alo_g[go];
        }
        // load B tile (16 x 64) with on-the-fly tf32 split
#pragma unroll
        for (int l = 0; l < 4; l++) {
            int lin = tid + l * 256;
            int r = lin >> 6;
            float v = g_comb[(size_t)(j0 + r) * BP + bsrc[l]];
            float hi = tf32_rna(v);
            float lo = tf32_rna(v - hi);
            sBhi[r][bcol[l]] = hi;
            sBlo[r][bcol[l]] = lo;
        }
        __syncthreads();

#pragma unroll
        for (int ks = 0; ks < 16; ks += 8) {
            uint32_t ah[2][4], al[2][4], bh[4][2], bl[4][2];
#pragma unroll
            for (int mt = 0; mt < 2; mt++) {
                int mb = wm * 32 + mt * 16 + lr;
                ah[mt][0] = __float_as_uint(sAhi[ks + lc][mb]);
                ah[mt][1] = __float_as_uint(sAhi[ks + lc][mb + 8]);
                ah[mt][2] = __float_as_uint(sAhi[ks + lc + 4][mb]);
                ah[mt][3] = __float_as_uint(sAhi[ks + lc + 4][mb + 8]);
                al[mt][0] = __float_as_uint(sAlo[ks + lc][mb]);
                al[mt][1] = __float_as_uint(sAlo[ks + lc][mb + 8]);
                al[mt][2] = __float_as_uint(sAlo[ks + lc + 4][mb]);
                al[mt][3] = __float_as_uint(sAlo[ks + lc + 4][mb + 8]);
            }
#pragma unroll
            for (int nt = 0; nt < 4; nt++) {
                int nb = wn * 32 + nt * 8 + lr;
                bh[nt][0] = __float_as_uint(sBhi[ks + lc][nb]);
                bh[nt][1] = __float_as_uint(sBhi[ks + lc + 4][nb]);
                bl[nt][0] = __float_as_uint(sBlo[ks + lc][nb]);
                bl[nt][1] = __float_as_uint(sBlo[ks + lc + 4][nb]);
            }
#pragma unroll
            for (int mt = 0; mt < 2; mt++)
#pragma unroll
                for (int nt = 0; nt < 4; nt++) {
                    MMA_TF32(acc[mt][nt], ah[mt], bh[nt]);
                    MMA_TF32(acc[mt][nt], ah[mt], bl[nt]);
                    MMA_TF32(acc[mt][nt], al[mt], bh[nt]);
                }
        }
        __syncthreads();
    }

    // epilogue: scatter to S
    int k = kmap[kk];
#pragma unroll
    for (int mt = 0; mt < 2; mt++)
#pragma unroll
        for (int nt = 0; nt < 4; nt++) {
            int i_row = i0 + wm * 32 + mt * 16 + lr;
            int c = c0 + wn * 32 + nt * 8 + 2 * lc;
            int b = c / cols_per_b;
            int p = c - b * cols_per_b;
            size_t off = (size_t)i_row * (BB * KP) + (size_t)b * KP + k * P + col_off + p;
            *(float2*)&g_S[off] = make_float2(acc[mt][nt][0], acc[mt][nt][1]);
            size_t off2 = off + (size_t)8 * BB * KP;
            *(float2*)&g_S[off2] = make_float2(acc[mt][nt][2], acc[mt][nt][3]);
        }
}

#define MICRO_FMA(a, b)                                                        \
    acc[0][0] += a.x * b.x; acc[0][1] += a.x * b.y;                            \
    acc[0][2] += a.x * b.z; acc[0][3] += a.x * b.w;                            \
    acc[1][0] += a.y * b.x; acc[1][1] += a.y * b.y;                            \
    acc[1][2] += a.y * b.z; acc[1][3] += a.y * b.w;                            \
    acc[2][0] += a.z * b.x; acc[2][1] += a.z * b.y;                            \
    acc[2][2] += a.z * b.z; acc[2][3] += a.z * b.w;                            \
    acc[3][0] += a.w * b.x; acc[3][1] += a.w * b.y;                            \
    acc[3][2] += a.w * b.z; acc[3][3] += a.w * b.w;

// zr = sigmoid(S @ gW + gb); z -> g_z, r*h -> comb[:, Pin:] AND into the
// identity S slices (k=0 and k=3), so S stays consistent with comb2 = [x, r*h].
__global__ void __launch_bounds__(256) k_gate_gemm(const float* __restrict__ W,
                                                   const float* __restrict__ bias,
                                                   const float* __restrict__ h, int P) {
    int KP = 6 * P;
    int m0 = blockIdx.y * 64, n0 = blockIdx.x * 64;
    __shared__ __align__(16) float As[12][68];
    __shared__ __align__(16) float Bs[12][64];
    int tid = threadIdx.x, tx = tid & 15, ty = tid >> 4;
    float acc[4][4] = {};
    for (int k0 = 0; k0 < KP; k0 += 12) {
#pragma unroll
        for (int l = 0; l < 3; l++) {
            int idx = tid + l * 256;
            int r = idx / 12, cc = idx - r * 12;
            As[cc][r] = g_S[(size_t)(m0 + r) * KP + k0 + cc];
            int r2 = idx >> 6, c2 = idx & 63;
            Bs[r2][c2] = W[(k0 + r2) * 128 + n0 + c2];
        }
        __syncthreads();
#pragma unroll
        for (int q = 0; q < 12; q++) {
            float4 a = *(const float4*)&As[q][ty * 4];
            float4 b = *(const float4*)&Bs[q][tx * 4];
            MICRO_FMA(a, b)
        }
        __syncthreads();
    }
    int Pin = P - HH;
#pragma unroll
    for (int r = 0; r < 4; r++) {
        int m = m0 + ty * 4 + r;
#pragma unroll
        for (int cc = 0; cc < 4; cc++) {
            int n = n0 + tx * 4 + cc;
            float v = acc[r][cc] + bias[n];
            v = 1.f / (1.f + expf(-v));
            if (n < HH) {
                g_z[m * HH + n] = v;
            } else {
                int hc = n - HH;
                float rh = v * h[m * HH + hc];
                g_comb[(size_t)m * P + Pin + hc] = rh;
                size_t sbase = (size_t)m * KP;
                g_S[sbase + Pin + hc] = rh;           // k = 0 (identity)
                g_S[sbase + 3 * P + Pin + hc] = rh;   // k = 3 (identity)
            }
        }
    }
}

// n = tanh(S2 @ uW + ub); h = z*n + (1-z)*h   (in place)
__global__ void __launch_bounds__(256) k_update_gemm(const float* __restrict__ W,
                                                     const float* __restrict__ bias,
                                                     float* __restrict__ h, int P) {
    int KP = 6 * P;
    int m0 = blockIdx.y * 64;
    __shared__ __align__(16) float As[12][68];
    __shared__ __align__(16) float Bs[12][64];
    int tid = threadIdx.x, tx = tid & 15, ty = tid >> 4;
    float acc[4][4] = {};
    for (int k0 = 0; k0 < KP; k0 += 12) {
#pragma unroll
        for (int l = 0; l < 3; l++) {
            int idx = tid + l * 256;
            int r = idx / 12, cc = idx - r * 12;
            As[cc][r] = g_S[(size_t)(m0 + r) * KP + k0 + cc];
            int r2 = idx >> 6, c2 = idx & 63;
            Bs[r2][c2] = W[(k0 + r2) * HH + c2];
        }
        __syncthreads();
#pragma unroll
        for (int q = 0; q < 12; q++) {
            float4 a = *(const float4*)&As[q][ty * 4];
            float4 b = *(const float4*)&Bs[q][tx * 4];
            MICRO_FMA(a, b)
        }
        __syncthreads();
    }
#pragma unroll
    for (int r = 0; r < 4; r++) {
        int m = m0 + ty * 4 + r;
#pragma unroll
        for (int cc = 0; cc < 4; cc++) {
            int n = tx * 4 + cc;
            float nv = tanhf(acc[r][cc] + bias[n]);
            float zv = g_z[m * HH + n];
            float hv = h[m * HH + n];
            h[m * HH + n] = zv * nv + (1.f - zv) * hv;
        }
    }
}

// y = h1 @ projW + projb; also write output slice t.  out layout [B, HOR, N, C]
__global__ void k_proj(const float* __restrict__ h1, const float* __restrict__ Wp,
                       const float* __restrict__ bp, float* __restrict__ out, int t) {
    int e = blockIdx.x * blockDim.x + threadIdx.x;
    if (e >= NN * BB * CC) return;
    int c = e & 1;
    int m = e >> 1;
    float s = bp[c];
#pragma unroll
    for (int hh = 0; hh < HH; hh++) s += h1[m * HH + hh] * Wp[hh * CC + c];
    g_y[e] = s;
    int i = m >> 6, b = m & 63;
    out[(((size_t)b * TT + t) * NN + i) * CC + c] = s;
}

// ---------------- host orchestration ----------------
static void run_cell(const float* xin, int Pin, float* h,
                     const float* gW, const float* gb,
                     const float* uW, const float* ub) {
    int P = Pin + HH;
    int total = NN * BB * P;
    k_build_comb<<<(total + 255) / 256, 256>>>(xin, h, Pin, P, 6 * P);
    // GCN1: full comb -> all non-identity S slices
    k_gcn_mma<<<dim3(BB * P / 64, 8, 4), 256>>>(P, P, 0);
    k_gate_gemm<<<dim3(2, 1024), 256>>>(gW, gb, h, P);
    // GCN2: only h-columns changed (comb2 = [x, r*h]); x-columns of S reused
    k_gcn_mma<<<dim3(BB * HH / 64, 8, 4), 256>>>(P, HH, Pin);
    k_update_gemm<<<dim3(1, 1024), 256>>>(uW, ub, h, P);
}

extern "C" void kernel_launch(void* const* d_in, const int* in_sizes, int n_in,
                              void* d_out, int out_size) {
    const float* x = (const float*)d_in[0];
    const float* G = (const float*)d_in[1];
    const float* gW[4] = {(const float*)d_in[2], (const float*)d_in[6],
                          (const float*)d_in[10], (const float*)d_in[14]};
    const float* gb[4] = {(const float*)d_in[3], (const float*)d_in[7],
                          (const float*)d_in[11], (const float*)d_in[15]};
    const float* uW[4] = {(const float*)d_in[4], (const float*)d_in[8],
                          (const float*)d_in[12], (const float*)d_in[16]};
    const float* ub[4] = {(const float*)d_in[5], (const float*)d_in[9],
                          (const float*)d_in[13], (const float*)d_in[17]};
    const float* projW = (const float*)d_in[18];
    const float* projb = (const float*)d_in[19];
    float* out = (float*)d_out;

    float *h0, *h1, *y, *xT;
    cudaGetSymbolAddress((void**)&h0, g_h0);
    cudaGetSymbolAddress((void**)&h1, g_h1);
    cudaGetSymbolAddress((void**)&y, g_y);
    cudaGetSymbolAddress((void**)&xT, g_xT);

    k_transpose_x<<<(TT * NN * BB * CC + 255) / 256, 256>>>(x);
    k_transpose_G<<<dim3(32, 32, 4), dim3(32, 8)>>>(G);
    k_zero<<<(NN * BB * HH + 255) / 256, 256>>>(h0, NN * BB * HH);
    k_zero<<<(NN * BB * HH + 255) / 256, 256>>>(h1, NN * BB * HH);
    k_zero<<<(NN * BB * CC + 255) / 256, 256>>>(y, NN * BB * CC);

    // encoder: 2 layers, 12 steps (interleaved so only current h0 is needed)
    for (int t = 0; t < TT; t++) {
        run_cell(xT + (size_t)t * NN * BB * CC, CC, h0, gW[0], gb[0], uW[0], ub[0]);
        run_cell(h0, HH, h1, gW[1], gb[1], uW[1], ub[1]);
    }
    // decoder: states continue from encoder finals (h0, h1 reused in place)
    for (int t = 0; t < TT; t++) {
        run_cell(y, CC, h0, gW[2], gb[2], uW[2], ub[2]);
        run_cell(h0, HH, h1, gW[3], gb[3], uW[3], ub[3]);
        k_proj<<<(NN * BB * CC + 255) / 256, 256>>>(h1, projW, projb, out, t);
    }
}

// round 7
// speedup vs baseline: 1.7424x; 1.1457x over previous
#include <cuda_runtime.h>
#include <math.h>
#include <stdint.h>

#define NN 1024
#define BB 64
#define TT 12
#define HH 64
#define CC 2

// ---------------- static device scratch ----------------
__device__ float g_xT[TT * NN * BB * CC];
__device__ float g_GT[4 * NN * NN];                // non-identity supports, transposed [kk][j][i], fp32
__device__ float g_comb[NN * BB * 128];            // [i][b][p]
__device__ float g_S[NN * BB * 768];               // [i][b][k*P+p]
__device__ float g_z[NN * BB * HH];
__device__ float g_h0[NN * BB * HH];
__device__ float g_h1[NN * BB * HH];
__device__ float g_y[NN * BB * CC];

__device__ __forceinline__ float tf32_rna(float v) {
    uint32_t u;
    asm("cvt.rna.tf32.f32 %0, %1;" : "=r"(u) : "f"(v));
    return __uint_as_float(u);
}

#define SPLIT(v, hi_u, lo_u) do {                                              \
    float _h = tf32_rna(v);                                                    \
    (hi_u) = __float_as_uint(_h);                                              \
    (lo_u) = __float_as_uint(tf32_rna((v) - _h));                              \
} while (0)

#define MMA_TF32(d, a, b)                                                      \
    asm volatile(                                                              \
        "mma.sync.aligned.m16n8k8.row.col.f32.tf32.tf32.f32 "                  \
        "{%0,%1,%2,%3}, {%4,%5,%6,%7}, {%8,%9}, {%0,%1,%2,%3};"                \
        : "+f"(d[0]), "+f"(d[1]), "+f"(d[2]), "+f"(d[3])                       \
        : "r"(a[0]), "r"(a[1]), "r"(a[2]), "r"(a[3]), "r"(b[0]), "r"(b[1]));

#define CP16(dst_u32, src_ptr)                                                 \
    asm volatile("cp.async.cg.shared.global [%0], [%1], 16;" ::                \
                 "r"(dst_u32), "l"(src_ptr))
#define CP4(dst_u32, src_ptr)                                                  \
    asm volatile("cp.async.ca.shared.global [%0], [%1], 4;" ::                 \
                 "r"(dst_u32), "l"(src_ptr))
#define CP_COMMIT() asm volatile("cp.async.commit_group;")
#define CP_WAIT1() asm volatile("cp.async.wait_group 1;")
#define CP_WAIT0() asm volatile("cp.async.wait_group 0;")

// ---------------- utility kernels ----------------
__global__ void k_zero(float* __restrict__ p, int n) {
    int e = blockIdx.x * blockDim.x + threadIdx.x;
    if (e < n) p[e] = 0.f;
}

__global__ void k_transpose_x(const float* __restrict__ x) {
    int e = blockIdx.x * blockDim.x + threadIdx.x;
    if (e >= TT * NN * BB * CC) return;
    int c = e % CC;
    int b = (e / CC) % BB;
    int i = (e / (CC * BB)) % NN;
    int t = e / (CC * BB * NN);
    g_xT[e] = x[(((size_t)b * TT + t) * NN + i) * CC + c];
}

__global__ void k_transpose_G(const float* __restrict__ G) {
    __shared__ float tile[32][33];
    const int kmap[4] = {1, 2, 4, 5};
    int kk = blockIdx.z;
    const float* A = G + (size_t)kmap[kk] * NN * NN;
    float* Bp = g_GT + (size_t)kk * NN * NN;
    int i0 = blockIdx.y * 32, j0 = blockIdx.x * 32;
#pragma unroll
    for (int s = 0; s < 32; s += 8)
        tile[threadIdx.y + s][threadIdx.x] =
            A[(size_t)(i0 + threadIdx.y + s) * NN + j0 + threadIdx.x];
    __syncthreads();
#pragma unroll
    for (int s = 0; s < 32; s += 8)
        Bp[(size_t)(j0 + threadIdx.y + s) * NN + i0 + threadIdx.x] =
            tile[threadIdx.x][threadIdx.y + s];
}

__global__ void k_build_comb(const float* __restrict__ xin, const float* __restrict__ h,
                             int Pin, int P, int KP) {
    int e = blockIdx.x * blockDim.x + threadIdx.x;
    int total = NN * BB * P;
    if (e >= total) return;
    int p = e % P;
    int ib = e / P;
    float v = (p < Pin) ? xin[ib * Pin + p] : h[ib * HH + (p - Pin)];
    g_comb[e] = v;
    size_t base = (size_t)ib * KP;
    g_S[base + p] = v;            // k = 0 (identity)
    g_S[base + 3 * P + p] = v;    // k = 3 (identity)
}

// ---------------- GCN GEMM: 3xTF32, split-at-load, cp.async double buffer ----
// Block tile 128(i) x 128(c); 8 warps, each 32(i) x 64(c). BLK_J=16.
// A tile: 16B cp.async (always aligned: stride NN, i0 mult of 128).
// B tile: 4B cp.async per element (column mapping makes 16B alignment
//         impossible when P=66 / col_off=2).
__global__ void __launch_bounds__(256, 2) k_gcn_mma(int P, int cols_per_b, int col_off) {
    const int kmap[4] = {1, 2, 4, 5};
    int kk = blockIdx.z;
    int KP = 6 * P, BP = BB * P;
    const float* Ag = g_GT + (size_t)kk * NN * NN;
    int i0 = blockIdx.y * 128, c0 = blockIdx.x * 128;

    __shared__ __align__(16) float sA[2][16][136];
    __shared__ __align__(16) float sB[2][16][136];

    int tid = threadIdx.x, w = tid >> 5, lane = tid & 31, lr = lane >> 2, lc = lane & 3;
    int wm = w & 3, wn = w >> 2;   // warp tile origin (wm*32 i, wn*64 c)

    uint32_t sA_u = (uint32_t)__cvta_generic_to_shared(&sA[0][0][0]);
    uint32_t sB_u = (uint32_t)__cvta_generic_to_shared(&sB[0][0][0]);
    const int STAGE_B = 16 * 136 * 4;   // 8704 bytes per stage

    // A copy: 2 x 16B slots per thread
    const float* aptr[2];
    uint32_t adst[2];
#pragma unroll
    for (int l = 0; l < 2; l++) {
        int lin = tid + l * 256;
        int r = lin >> 5, c4 = (lin & 31) * 4;
        aptr[l] = Ag + (size_t)r * NN + i0 + c4;
        adst[l] = sA_u + (r * 136 + c4) * 4;
    }
    // B copy: 8 x 4B slots per thread (element offsets within one j-block)
    int boff[8];
    uint32_t bdst[8];
#pragma unroll
    for (int l = 0; l < 8; l++) {
        int lin = tid + l * 256;
        int r = lin >> 7, c = lin & 127;
        int gc = c0 + c;
        int b = gc / cols_per_b;
        int p = gc - b * cols_per_b;
        boff[l] = r * BP + b * P + col_off + p;
        bdst[l] = sB_u + (r * 136 + c) * 4;
    }

    float acc[2][8][4] = {};

    // prologue: tile 0 -> stage 0
#pragma unroll
    for (int l = 0; l < 2; l++) CP16(adst[l], aptr[l]);
#pragma unroll
    for (int l = 0; l < 8; l++) CP4(bdst[l], g_comb + boff[l]);
    CP_COMMIT();

    const int NTILES = NN / 16;
    for (int jt = 0; jt < NTILES; jt++) {
        int st = jt & 1;
        if (jt + 1 < NTILES) {
            uint32_t so = (st ^ 1) * STAGE_B;
            const float* bbase = g_comb + (size_t)(jt + 1) * 16 * BP;
            size_t arow = (size_t)(jt + 1) * 16 * NN;
#pragma unroll
            for (int l = 0; l < 2; l++) CP16(adst[l] + so, aptr[l] + arow);
#pragma unroll
            for (int l = 0; l < 8; l++) CP4(bdst[l] + so, bbase + boff[l]);
            CP_COMMIT();
            CP_WAIT1();
        } else {
            CP_WAIT0();
        }
        __syncthreads();

#pragma unroll
        for (int ks = 0; ks < 16; ks += 8) {
            uint32_t ah[2][4], al[2][4];
#pragma unroll
            for (int mt = 0; mt < 2; mt++) {
                int mb = wm * 32 + mt * 16 + lr;
                float v0 = sA[st][ks + lc][mb];
                float v1 = sA[st][ks + lc][mb + 8];
                float v2 = sA[st][ks + lc + 4][mb];
                float v3 = sA[st][ks + lc + 4][mb + 8];
                SPLIT(v0, ah[mt][0], al[mt][0]);
                SPLIT(v1, ah[mt][1], al[mt][1]);
                SPLIT(v2, ah[mt][2], al[mt][2]);
                SPLIT(v3, ah[mt][3], al[mt][3]);
            }
#pragma unroll
            for (int nt = 0; nt < 8; nt++) {
                int nb = wn * 64 + nt * 8 + lr;
                float u0 = sB[st][ks + lc][nb];
                float u1 = sB[st][ks + lc + 4][nb];
                uint32_t bh[2], bl[2];
                SPLIT(u0, bh[0], bl[0]);
                SPLIT(u1, bh[1], bl[1]);
#pragma unroll
                for (int mt = 0; mt < 2; mt++) {
                    MMA_TF32(acc[mt][nt], ah[mt], bh);
                    MMA_TF32(acc[mt][nt], ah[mt], bl);
                    MMA_TF32(acc[mt][nt], al[mt], bh);
                }
            }
        }
        __syncthreads();
    }

    int k = kmap[kk];
#pragma unroll
    for (int mt = 0; mt < 2; mt++)
#pragma unroll
        for (int nt = 0; nt < 8; nt++) {
            int i_row = i0 + wm * 32 + mt * 16 + lr;
            int c = c0 + wn * 64 + nt * 8 + 2 * lc;
            int b = c / cols_per_b;
            int p = c - b * cols_per_b;
            size_t off = (size_t)i_row * (BB * KP) + (size_t)b * KP + k * P + col_off + p;
            *(float2*)&g_S[off] = make_float2(acc[mt][nt][0], acc[mt][nt][1]);
            size_t off2 = off + (size_t)8 * BB * KP;
            *(float2*)&g_S[off2] = make_float2(acc[mt][nt][2], acc[mt][nt][3]);
        }
}

// ---------------- dense GEMMs on tensor cores (3xTF32, split-at-load) -------
// Block 128(m) x 64(n); 8 warps 32x32 (wm 0..3, wn 0..1). K tiled by 16 w/ guard.

// zr = sigmoid(S @ gW + gb); z -> g_z; rh -> comb h-cols + identity S slices.
__global__ void __launch_bounds__(256) k_gate_mma(const float* __restrict__ W,
                                                  const float* __restrict__ bias,
                                                  const float* __restrict__ h, int P) {
    int KP = 6 * P;
    int m0 = blockIdx.y * 128, n0 = blockIdx.x * 64;
    __shared__ __align__(16) float sS[16][136];
    __shared__ __align__(16) float sW[16][72];
    int tid = threadIdx.x, w = tid >> 5, lane = tid & 31, lr = lane >> 2, lc = lane & 3;
    int wm = w & 3, wn = w >> 2;
    float acc[2][4][4] = {};
    int niter = (KP + 15) / 16;

    for (int it = 0; it < niter; it++) {
        int k0 = it * 16;
#pragma unroll
        for (int l = 0; l < 2; l++) {
            int lin = tid + l * 256;
            int ml = lin >> 2, kg = lin & 3;
            float4 v = make_float4(0.f, 0.f, 0.f, 0.f);
            int kb = k0 + kg * 4;
            if (kb < KP) v = *(const float4*)&g_S[(size_t)(m0 + ml) * KP + kb];
            sS[kg * 4 + 0][ml] = v.x;
            sS[kg * 4 + 1][ml] = v.y;
            sS[kg * 4 + 2][ml] = v.z;
            sS[kg * 4 + 3][ml] = v.w;
        }
        {
            int kl = tid >> 4, ng = (tid & 15) * 4;
            float4 v = make_float4(0.f, 0.f, 0.f, 0.f);
            if (k0 + kl < KP) v = *(const float4*)&W[(size_t)(k0 + kl) * 128 + n0 + ng];
            *(float4*)&sW[kl][ng] = v;
        }
        __syncthreads();
#pragma unroll
        for (int ks = 0; ks < 16; ks += 8) {
            uint32_t ah[2][4], al[2][4];
#pragma unroll
            for (int mt = 0; mt < 2; mt++) {
                int mb = wm * 32 + mt * 16 + lr;
                float v0 = sS[ks + lc][mb], v1 = sS[ks + lc][mb + 8];
                float v2 = sS[ks + lc + 4][mb], v3 = sS[ks + lc + 4][mb + 8];
                SPLIT(v0, ah[mt][0], al[mt][0]);
                SPLIT(v1, ah[mt][1], al[mt][1]);
                SPLIT(v2, ah[mt][2], al[mt][2]);
                SPLIT(v3, ah[mt][3], al[mt][3]);
            }
#pragma unroll
            for (int nt = 0; nt < 4; nt++) {
                int nb = wn * 32 + nt * 8 + lr;
                float u0 = sW[ks + lc][nb], u1 = sW[ks + lc + 4][nb];
                uint32_t bh[2], bl[2];
                SPLIT(u0, bh[0], bl[0]);
                SPLIT(u1, bh[1], bl[1]);
#pragma unroll
                for (int mt = 0; mt < 2; mt++) {
                    MMA_TF32(acc[mt][nt], ah[mt], bh);
                    MMA_TF32(acc[mt][nt], ah[mt], bl);
                    MMA_TF32(acc[mt][nt], al[mt], bh);
                }
            }
        }
        __syncthreads();
    }

    int Pin = P - HH;
#pragma unroll
    for (int mt = 0; mt < 2; mt++)
#pragma unroll
        for (int nt = 0; nt < 4; nt++) {
#pragma unroll
            for (int rg = 0; rg < 4; rg++) {
                int m = m0 + wm * 32 + mt * 16 + lr + (rg >> 1) * 8;
                int n = n0 + wn * 32 + nt * 8 + 2 * lc + (rg & 1);
                float v = acc[mt][nt][rg] + bias[n];
                v = 1.f / (1.f + expf(-v));
                if (n < HH) {
                    g_z[m * HH + n] = v;
                } else {
                    int hc = n - HH;
                    float rh = v * h[m * HH + hc];
                    g_comb[(size_t)m * P + Pin + hc] = rh;
                    size_t sbase = (size_t)m * KP;
                    g_S[sbase + Pin + hc] = rh;           // k = 0 (identity)
                    g_S[sbase + 3 * P + Pin + hc] = rh;   // k = 3 (identity)
                }
            }
        }
}

// n = tanh(S2 @ uW + ub); h = z*n + (1-z)*h
__global__ void __launch_bounds__(256) k_update_mma(const float* __restrict__ W,
                                                    const float* __restrict__ bias,
                                                    float* __restrict__ h, int P) {
    int KP = 6 * P;
    int m0 = blockIdx.y * 128;
    __shared__ __align__(16) float sS[16][136];
    __shared__ __align__(16) float sW[16][72];
    int tid = threadIdx.x, w = tid >> 5, lane = tid & 31, lr = lane >> 2, lc = lane & 3;
    int wm = w & 3, wn = w >> 2;
    float acc[2][4][4] = {};
    int niter = (KP + 15) / 16;

    for (int it = 0; it < niter; it++) {
        int k0 = it * 16;
#pragma unroll
        for (int l = 0; l < 2; l++) {
            int lin = tid + l * 256;
            int ml = lin >> 2, kg = lin & 3;
            float4 v = make_float4(0.f, 0.f, 0.f, 0.f);
            int kb = k0 + kg * 4;
            if (kb < KP) v = *(const float4*)&g_S[(size_t)(m0 + ml) * KP + kb];
            sS[kg * 4 + 0][ml] = v.x;
            sS[kg * 4 + 1][ml] = v.y;
            sS[kg * 4 + 2][ml] = v.z;
            sS[kg * 4 + 3][ml] = v.w;
        }
        {
            int kl = tid >> 4, ng = (tid & 15) * 4;
            float4 v = make_float4(0.f, 0.f, 0.f, 0.f);
            if (k0 + kl < KP) v = *(const float4*)&W[(size_t)(k0 + kl) * HH + ng];
            *(float4*)&sW[kl][ng] = v;
        }
        __syncthreads();
#pragma unroll
        for (int ks = 0; ks < 16; ks += 8) {
            uint32_t ah[2][4], al[2][4];
#pragma unroll
            for (int mt = 0; mt < 2; mt++) {
                int mb = wm * 32 + mt * 16 + lr;
                float v0 = sS[ks + lc][mb], v1 = sS[ks + lc][mb + 8];
                float v2 = sS[ks + lc + 4][mb], v3 = sS[ks + lc + 4][mb + 8];
                SPLIT(v0, ah[mt][0], al[mt][0]);
                SPLIT(v1, ah[mt][1], al[mt][1]);
                SPLIT(v2, ah[mt][2], al[mt][2]);
                SPLIT(v3, ah[mt][3], al[mt][3]);
            }
#pragma unroll
            for (int nt = 0; nt < 4; nt++) {
                int nb = wn * 32 + nt * 8 + lr;
                float u0 = sW[ks + lc][nb], u1 = sW[ks + lc + 4][nb];
                uint32_t bh[2], bl[2];
                SPLIT(u0, bh[0], bl[0]);
                SPLIT(u1, bh[1], bl[1]);
#pragma unroll
                for (int mt = 0; mt < 2; mt++) {
                    MMA_TF32(acc[mt][nt], ah[mt], bh);
                    MMA_TF32(acc[mt][nt], ah[mt], bl);
                    MMA_TF32(acc[mt][nt], al[mt], bh);
                }
            }
        }
        __syncthreads();
    }

#pragma unroll
    for (int mt = 0; mt < 2; mt++)
#pragma unroll
        for (int nt = 0; nt < 4; nt++) {
#pragma unroll
            for (int rg = 0; rg < 4; rg++) {
                int m = m0 + wm * 32 + mt * 16 + lr + (rg >> 1) * 8;
                int n = wn * 32 + nt * 8 + 2 * lc + (rg & 1);
                float nv = tanhf(acc[mt][nt][rg] + bias[n]);
                float zv = g_z[m * HH + n];
                float hv = h[m * HH + n];
                h[m * HH + n] = zv * nv + (1.f - zv) * hv;
            }
        }
}

// y = h1 @ projW + projb; also write output slice t.  out layout [B, HOR, N, C]
__global__ void k_proj(const float* __restrict__ h1, const float* __restrict__ Wp,
                       const float* __restrict__ bp, float* __restrict__ out, int t) {
    int e = blockIdx.x * blockDim.x + threadIdx.x;
    if (e >= NN * BB * CC) return;
    int c = e & 1;
    int m = e >> 1;
    float s = bp[c];
#pragma unroll
    for (int hh = 0; hh < HH; hh++) s += h1[m * HH + hh] * Wp[hh * CC + c];
    g_y[e] = s;
    int i = m >> 6, b = m & 63;
    out[(((size_t)b * TT + t) * NN + i) * CC + c] = s;
}

// ---------------- host orchestration ----------------
static void run_cell(const float* xin, int Pin, float* h,
                     const float* gW, const float* gb,
                     const float* uW, const float* ub) {
    int P = Pin + HH;
    int total = NN * BB * P;
    k_build_comb<<<(total + 255) / 256, 256>>>(xin, h, Pin, P, 6 * P);
    // GCN1: full comb -> all non-identity S slices
    k_gcn_mma<<<dim3(BB * P / 128, 8, 4), 256>>>(P, P, 0);
    k_gate_mma<<<dim3(2, 512), 256>>>(gW, gb, h, P);
    // GCN2: only h-columns changed; x-columns of S reused
    k_gcn_mma<<<dim3(BB * HH / 128, 8, 4), 256>>>(P, HH, Pin);
    k_update_mma<<<dim3(1, 512), 256>>>(uW, ub, h, P);
}

extern "C" void kernel_launch(void* const* d_in, const int* in_sizes, int n_in,
                              void* d_out, int out_size) {
    const float* x = (const float*)d_in[0];
    const float* G = (const float*)d_in[1];
    const float* gW[4] = {(const float*)d_in[2], (const float*)d_in[6],
                          (const float*)d_in[10], (const float*)d_in[14]};
    const float* gb[4] = {(const float*)d_in[3], (const float*)d_in[7],
                          (const float*)d_in[11], (const float*)d_in[15]};
    const float* uW[4] = {(const float*)d_in[4], (const float*)d_in[8],
                          (const float*)d_in[12], (const float*)d_in[16]};
    const float* ub[4] = {(const float*)d_in[5], (const float*)d_in[9],
                          (const float*)d_in[13], (const float*)d_in[17]};
    const float* projW = (const float*)d_in[18];
    const float* projb = (const float*)d_in[19];
    float* out = (float*)d_out;

    float *h0, *h1, *y, *xT;
    cudaGetSymbolAddress((void**)&h0, g_h0);
    cudaGetSymbolAddress((void**)&h1, g_h1);
    cudaGetSymbolAddress((void**)&y, g_y);
    cudaGetSymbolAddress((void**)&xT, g_xT);

    k_transpose_x<<<(TT * NN * BB * CC + 255) / 256, 256>>>(x);
    k_transpose_G<<<dim3(32, 32, 4), dim3(32, 8)>>>(G);
    k_zero<<<(NN * BB * HH + 255) / 256, 256>>>(h0, NN * BB * HH);
    k_zero<<<(NN * BB * HH + 255) / 256, 256>>>(h1, NN * BB * HH);
    k_zero<<<(NN * BB * CC + 255) / 256, 256>>>(y, NN * BB * CC);

    for (int t = 0; t < TT; t++) {
        run_cell(xT + (size_t)t * NN * BB * CC, CC, h0, gW[0], gb[0], uW[0], ub[0]);
        run_cell(h0, HH, h1, gW[1], gb[1], uW[1], ub[1]);
    }
    for (int t = 0; t < TT; t++) {
        run_cell(y, CC, h0, gW[2], gb[2], uW[2], ub[2]);
        run_cell(h0, HH, h1, gW[3], gb[3], uW[3], ub[3]);
        k_proj<<<(NN * BB * CC + 255) / 256, 256>>>(h1, projW, projb, out, t);
    }
}